// round 4
// baseline (speedup 1.0000x reference)
#include <cuda_runtime.h>

#define S_NODES 8192
#define NN      8384
#define CH      128
#define BB      2
#define EE      262144

// ---------------- scratch (device globals; no allocation allowed) -----------
__device__ float g_h0[BB * NN * CH];
__device__ float g_h1[BB * NN * CH];
__device__ float g_q[BB * NN];
__device__ float g_p[BB * NN];
__device__ float g_dinvI[BB * NN];   // gcn norm: rsqrt(intra_in_deg + 1)
__device__ float g_dinvX[BB * NN];   // inter: 1/deg or 0
__device__ int   g_cntI[BB * NN];
__device__ int   g_cntX[BB * NN];
__device__ int   g_pos[BB * NN];
__device__ int   g_rowptr[BB * (NN + 1)];
__device__ int   g_srcs[BB * EE];

__device__ __forceinline__ float tanh_fast(float z) {
    float az = fabsf(z);
    float e  = __expf(2.0f * az);
    float r  = 1.0f - 2.0f / (e + 1.0f);
    return copysignf(r, z);
}

// ---------------- CSR build ------------------------------------------------
__global__ void k_zero() {
    int i = blockIdx.x * blockDim.x + threadIdx.x;
    if (i < BB * NN) { g_cntI[i] = 0; g_cntX[i] = 0; g_pos[i] = 0; }
}

__global__ void k_hist(const int* __restrict__ ei) {
    int i = blockIdx.x * blockDim.x + threadIdx.x;
    if (i >= BB * EE) return;
    int b = i / EE, e = i - b * EE;
    int s = ei[b * 2 * EE + e];
    int d = ei[b * 2 * EE + EE + e];
    bool intra = (s < S_NODES) == (d < S_NODES);
    if (intra) atomicAdd(&g_cntI[b * NN + d], 1);
    else       atomicAdd(&g_cntX[b * NN + d], 1);
}

// one block per batch: exclusive scan of (cntI+cntX) over NN nodes + dinv
__global__ void k_scan() {
    __shared__ int sh[1024];
    __shared__ int carry;
    int b = blockIdx.x;
    if (threadIdx.x == 0) carry = 0;
    __syncthreads();
    for (int base = 0; base < NN; base += 1024) {
        int i = base + threadIdx.x;
        int cI = 0, cX = 0, v = 0;
        if (i < NN) {
            cI = g_cntI[b * NN + i];
            cX = g_cntX[b * NN + i];
            v = cI + cX;
        }
        sh[threadIdx.x] = v;
        __syncthreads();
        for (int off = 1; off < 1024; off <<= 1) {
            int t = (threadIdx.x >= off) ? sh[threadIdx.x - off] : 0;
            __syncthreads();
            sh[threadIdx.x] += t;
            __syncthreads();
        }
        if (i < NN) {
            g_rowptr[b * (NN + 1) + i] = carry + sh[threadIdx.x] - v;  // exclusive
            g_dinvI[b * NN + i] = rsqrtf((float)(cI + 1));
            g_dinvX[b * NN + i] = (cX > 0) ? (1.0f / (float)cX) : 0.0f;
        }
        __syncthreads();
        if (threadIdx.x == 1023) carry += sh[1023];
        __syncthreads();
    }
    if (threadIdx.x == 0) g_rowptr[b * (NN + 1) + NN] = carry;
}

__global__ void k_scatter(const int* __restrict__ ei) {
    int i = blockIdx.x * blockDim.x + threadIdx.x;
    if (i >= BB * EE) return;
    int b = i / EE, e = i - b * EE;
    int s = ei[b * 2 * EE + e];
    int d = ei[b * 2 * EE + EE + e];
    int pos = g_rowptr[b * (NN + 1) + d] + atomicAdd(&g_pos[b * NN + d], 1);
    g_srcs[b * EE + pos] = s;
}

// sort each node's src segment by value -> deterministic FP accumulation order
// (duplicate src values contribute bitwise-identical terms, so value-sort is
//  a deterministic total order for the sum)
__global__ void k_sort() {
    __shared__ int buf[96 * 128];           // 48 KB, interleaved: elem k of thread t at [k*128+t]
    int n = blockIdx.x * blockDim.x + threadIdx.x;
    if (n >= BB * NN) return;
    int b = n / NN, v = n - b * NN;
    int beg = g_rowptr[b * (NN + 1) + v] + b * EE;
    int len = g_rowptr[b * (NN + 1) + v + 1] + b * EE - beg;
    if (len <= 1) return;
#define AA(k) buf[(k) * 128 + threadIdx.x]
    if (len <= 96) {
        for (int i = 0; i < len; i++) AA(i) = g_srcs[beg + i];
        for (int i = 1; i < len; i++) {
            int key = AA(i); int j = i - 1;
            while (j >= 0 && AA(j) > key) { AA(j + 1) = AA(j); j--; }
            AA(j + 1) = key;
        }
        for (int i = 0; i < len; i++) g_srcs[beg + i] = AA(i);
    } else {  // rare fallback (expected max in-degree ~65 for Poisson(31))
        for (int i = 1; i < len; i++) {
            int key = g_srcs[beg + i]; int j = i - 1;
            while (j >= 0 && g_srcs[beg + j] > key) { g_srcs[beg + j + 1] = g_srcs[beg + j]; j--; }
            g_srcs[beg + j + 1] = key;
        }
    }
#undef AA
}

// ---------------- per-node attention dots: q[v]=x·Wa, p[v]=x·Wb ------------
__global__ void k_dots(const float* __restrict__ x,
                       const float* __restrict__ WaS, const float* __restrict__ WbS,
                       const float* __restrict__ WaT, const float* __restrict__ WbT) {
    int t = blockIdx.x * blockDim.x + threadIdx.x;
    int w = t >> 5, lane = t & 31;
    if (w >= BB * NN) return;
    int v = w % NN;
    const float* Wa = (v < S_NODES) ? WaS : WaT;
    const float* Wb = (v < S_NODES) ? WbS : WbT;
    float4 xv = ((const float4*)x)[w * 32 + lane];
    float4 wa = ((const float4*)Wa)[lane];
    float4 wb = ((const float4*)Wb)[lane];
    float qs = xv.x * wa.x + xv.y * wa.y + xv.z * wa.z + xv.w * wa.w;
    float ps = xv.x * wb.x + xv.y * wb.y + xv.z * wb.z + xv.w * wb.w;
    #pragma unroll
    for (int o = 16; o > 0; o >>= 1) {
        qs += __shfl_xor_sync(0xffffffffu, qs, o);
        ps += __shfl_xor_sync(0xffffffffu, ps, o);
    }
    if (lane == 0) { g_q[w] = qs; g_p[w] = ps; }
}

// ---------------- gather (warp per dst node, float4 per lane) --------------
template <bool INTRA, bool RELU>
__global__ void k_gather(const float* __restrict__ xin, float* __restrict__ xout) {
    int t = blockIdx.x * blockDim.x + threadIdx.x;
    int w = t >> 5, lane = t & 31;
    if (w >= BB * NN) return;
    int b = w / NN;
    int v = w - b * NN;
    bool isS = v < S_NODES;
    float qv = g_q[w];
    float dv = INTRA ? g_dinvI[w] : g_dinvX[w];
    const float4* x4 = (const float4*)xin;
    float4 xv = x4[w * 32 + lane];
    float4 acc = make_float4(0.f, 0.f, 0.f, 0.f);

    int beg = g_rowptr[b * (NN + 1) + v];
    int end = g_rowptr[b * (NN + 1) + v + 1];
    const int* __restrict__ srcs = g_srcs + b * EE;
    for (int e = beg; e < end; e++) {
        int s = srcs[e];                         // uniform across warp -> broadcast
        bool sIsS = s < S_NODES;
        if ((sIsS == isS) == INTRA) {
            int sn = b * NN + s;
            float coef = tanh_fast(qv + g_p[sn]);
            coef *= INTRA ? (dv * g_dinvI[sn]) : dv;
            float4 xs = x4[sn * 32 + lane];
            acc.x += coef * xs.x; acc.y += coef * xs.y;
            acc.z += coef * xs.z; acc.w += coef * xs.w;
        }
    }
    if (INTRA) {  // self loop: alpha_self = tanh(q+p), norm = 1/deg = dinv^2
        float cs = tanh_fast(qv + g_p[w]) * dv * dv;
        acc.x += cs * xv.x; acc.y += cs * xv.y;
        acc.z += cs * xv.z; acc.w += cs * xv.w;
    }
    float4 o;
    o.x = xv.x + acc.x; o.y = xv.y + acc.y;
    o.z = xv.z + acc.z; o.w = xv.w + acc.w;
    if (RELU) {
        o.x = fmaxf(o.x, 0.f); o.y = fmaxf(o.y, 0.f);
        o.z = fmaxf(o.z, 0.f); o.w = fmaxf(o.w, 0.f);
    }
    ((float4*)xout)[w * 32 + lane] = o;
}

// ---------------- launch ---------------------------------------------------
extern "C" void kernel_launch(void* const* d_in, const int* in_sizes, int n_in,
                              void* d_out, int out_size) {
    const float* x   = (const float*)d_in[0];
    const int*   ei  = (const int*)d_in[1];
    const float* Wss = (const float*)d_in[2];
    const float* Wtt = (const float*)d_in[3];
    const float* Wst = (const float*)d_in[4];
    const float* Wts = (const float*)d_in[5];
    float* out = (float*)d_out;

    float *h0, *h1;
    cudaGetSymbolAddress((void**)&h0, g_h0);
    cudaGetSymbolAddress((void**)&h1, g_h1);

    // CSR build (depends only on edge_index; recomputed every call)
    k_zero<<<(BB * NN + 255) / 256, 256>>>();
    k_hist<<<(BB * EE + 255) / 256, 256>>>(ei);
    k_scan<<<BB, 1024>>>();
    k_scatter<<<(BB * EE + 255) / 256, 256>>>(ei);
    k_sort<<<(BB * NN + 127) / 128, 128>>>();

    int ng = (BB * NN * 32 + 255) / 256;   // warp-per-node grids

    // pass 0: intra, layer 0, relu   (W_ss / W_tt row 0)
    k_dots<<<ng, 256>>>(x, Wss, Wss + 128, Wtt, Wtt + 128);
    k_gather<true, true><<<ng, 256>>>(x, h0);

    // pass 1: inter, layer 0, relu
    // q: s-node <- W_ts[:C], t-node <- W_st[:C]; p: s-node <- W_st[C:], t-node <- W_ts[C:]
    k_dots<<<ng, 256>>>(h0, Wts, Wst + 128, Wst, Wts + 128);
    k_gather<false, true><<<ng, 256>>>(h0, h1);

    // pass 2: intra, layer 1, relu  (row 1 = offset 256)
    k_dots<<<ng, 256>>>(h1, Wss + 256, Wss + 256 + 128, Wtt + 256, Wtt + 256 + 128);
    k_gather<true, true><<<ng, 256>>>(h1, h0);

    // pass 3: inter, layer 1, no relu, write straight to d_out
    k_dots<<<ng, 256>>>(h0, Wts + 256, Wst + 256 + 128, Wst + 256, Wts + 256 + 128);
    k_gather<false, false><<<ng, 256>>>(h0, out);
}